// round 5
// baseline (speedup 1.0000x reference)
#include <cuda_runtime.h>
#include <cuda_fp16.h>
#include <cuda_bf16.h>
#include <cstdint>

// ---------------- problem constants ----------------
#define NS 2
#define CD 256
#define PD 4096            // 64*64
#define EPSF 1e-5f
#define LOG2E 1.4426950408889634f

// ---------------- device scratch (no runtime allocs allowed) ----------------
static __device__ __half   g_dot[(size_t)NS * PD * PD];   // 64 MiB: dot[n][pt][pi]
static __device__ uint8_t  g_Tn[(size_t)NS * PD * CD];    // normalized T, fp8 e4m3 x16, [n][p][c]
static __device__ uint8_t  g_In[(size_t)NS * PD * CD];    // normalized I, fp8 e4m3 x16, [n][p][c]
static __device__ float g_meanT[CD];
static __device__ float g_colmin[NS * PD];   // min over pt of raw=(1-dot)/2 per (n,pi); >=0
static __device__ float g_S[NS * PD];        // sum_pt exp(c1*(dot-dmax)) per (n,pi)

// ---------------- asm helpers (baseline sm_80/sm_89 ISA only) ----------------
__device__ __forceinline__ uint32_t smem_to_u32(const void* p) {
    uint32_t a;
    asm("{ .reg .u64 t; cvta.to.shared.u64 t, %1; cvt.u32.u64 %0, t; }" : "=r"(a) : "l"(p));
    return a;
}
#define CP_ASYNC16(dst, src) \
    asm volatile("cp.async.cg.shared.global [%0], [%1], 16;" :: "r"(dst), "l"(src) : "memory")
#define CP_COMMIT() asm volatile("cp.async.commit_group;" ::: "memory")
#define CP_WAIT(N)  asm volatile("cp.async.wait_group %0;" :: "n"(N) : "memory")

#define LDSM_X4(R, addr) \
    asm volatile("ldmatrix.sync.aligned.m8n8.x4.shared.b16 {%0,%1,%2,%3}, [%4];" \
        : "=r"((R)[0]), "=r"((R)[1]), "=r"((R)[2]), "=r"((R)[3]) : "r"(addr))

// fp8 e4m3 MMA: m16n8k32, A row-major (K-major), B col-major (K-major), f32 accum
#define MMA_FP8(D, A, B0, B1) \
    asm volatile("mma.sync.aligned.m16n8k32.row.col.f32.e4m3.e4m3.f32 " \
        "{%0,%1,%2,%3}, {%4,%5,%6,%7}, {%8,%9}, {%0,%1,%2,%3};" \
        : "+f"((D)[0]), "+f"((D)[1]), "+f"((D)[2]), "+f"((D)[3]) \
        : "r"((A)[0]), "r"((A)[1]), "r"((A)[2]), "r"((A)[3]), "r"(B0), "r"(B1))

// pack two floats -> e4m3x2 (lo = first elem, hi = second elem)
__device__ __forceinline__ uint16_t pack_e4m3(float lo, float hi) {
    uint16_t r;
    asm("cvt.rn.satfinite.e4m3x2.f32 %0, %1, %2;" : "=h"(r) : "f"(hi), "f"(lo));
    return r;
}
__device__ __forceinline__ float ex2(float x) {
    float r;
    asm("ex2.approx.ftz.f32 %0, %1;" : "=f"(r) : "f"(x));
    return r;
}
__device__ __forceinline__ float fexp(float x) {
    return ex2(fmaxf(x, -120.0f) * LOG2E);
}

// ---------------- kernel 1: meanT per channel (+ fused accumulator init) ----------------
__global__ void k_mean(const float* __restrict__ T) {
    int c = blockIdx.x;       // 256
    int tid = threadIdx.x;    // 256
    if (tid < 32) {           // 256 blocks x 32 = 8192 = NS*PD
        int i = c * 32 + tid;
        g_colmin[i] = 3.402823466e38f;
        g_S[i] = 0.0f;
    }
    float s = 0.0f;
    #pragma unroll
    for (int n = 0; n < NS; n++) {
        const float4* b4 = (const float4*)(T + ((size_t)n * CD + c) * PD);
        #pragma unroll
        for (int i = tid; i < PD / 4; i += 256) {
            float4 v = b4[i];
            s += v.x + v.y + v.z + v.w;
        }
    }
    __shared__ float sh[256];
    sh[tid] = s; __syncthreads();
    for (int o = 128; o > 0; o >>= 1) { if (tid < o) sh[tid] += sh[tid + o]; __syncthreads(); }
    if (tid == 0) g_meanT[c] = sh[0] * (1.0f / (float)(NS * PD));
}

// ---------------- kernel 2: center + normalize(+x16) + transpose -> fp8 ----------------
#define NP 32
#define BPITCH 260   // floats per p-row (256 + 4 pad)
__global__ void __launch_bounds__(256) k_norm2(const float* __restrict__ I,
                                               const float* __restrict__ T) {
    const float* X = blockIdx.z ? I : T;
    uint8_t* out = blockIdx.z ? g_In : g_Tn;
    int n = blockIdx.y;
    int p0 = blockIdx.x * NP;
    int tid = threadIdx.x;
    __shared__ float buf[NP][BPITCH];   // [p][c]
    __shared__ float nrm[8][NP];

    const float* base = X + (size_t)n * CD * PD + p0;
    #pragma unroll
    for (int it = 0; it < 8; it++) {
        int idx = it * 256 + tid;       // 2048 = 256 c * 8 float4
        int c = idx >> 3, j = idx & 7;
        float4 v = *(const float4*)(base + (size_t)c * PD + j * 4);
        float mc = g_meanT[c];
        buf[j * 4 + 0][c] = v.x - mc;
        buf[j * 4 + 1][c] = v.y - mc;
        buf[j * 4 + 2][c] = v.z - mc;
        buf[j * 4 + 3][c] = v.w - mc;
    }
    __syncthreads();
    {
        int p = tid >> 3, k = tid & 7;  // 32 p x 8 chunks
        float s = 0.0f;
        #pragma unroll
        for (int m = 0; m < 32; m++) { float v = buf[p][k * 32 + m]; s += v * v; }
        nrm[k][p] = s;
    }
    __syncthreads();
    if (tid < NP) {
        float t = 0.0f;
        #pragma unroll
        for (int k = 0; k < 8; k++) t += nrm[k][tid];
        nrm[0][tid] = rsqrtf(t) * 16.0f;   // x16 scale: e4m3 values ~O(1)
    }
    __syncthreads();
    uint8_t* ob = out + ((size_t)n * PD + p0) * CD;
    #pragma unroll
    for (int it = 0; it < 4; it++) {
        int idx = it * 256 + tid;       // 1024 = 32 p * 32 8-byte groups
        int p = idx >> 5, q = idx & 31;
        float sc = nrm[0][p];
        float4 v0 = *(float4*)&buf[p][q * 8];
        float4 v1 = *(float4*)&buf[p][q * 8 + 4];
        uint16_t h0 = pack_e4m3(v0.x * sc, v0.y * sc);
        uint16_t h1 = pack_e4m3(v0.z * sc, v0.w * sc);
        uint16_t h2 = pack_e4m3(v1.x * sc, v1.y * sc);
        uint16_t h3 = pack_e4m3(v1.z * sc, v1.w * sc);
        uint2 u;
        u.x = (uint32_t)h0 | ((uint32_t)h1 << 16);
        u.y = (uint32_t)h2 | ((uint32_t)h3 << 16);
        *(uint2*)(ob + (size_t)p * CD + q * 8) = u;
    }
}

// ---------------- kernel 3: persistent fp8 MMA GEMM, 128x256 tiles, cross-tile pipeline ----------------
#define BM 128
#define BN 256
#define PITCH 144                 // 128 fp8 bytes + 16B pad
#define ASZ (BM * PITCH)          // 18432
#define BSZ (BN * PITCH)          // 36864
#define STG (ASZ + BSZ)           // 55296
#define EPI_OFF (2 * STG)         // 110592
#define EPITCH 528                // epilogue fp16 row pitch (256*2 + 16)
#define GEMM_SMEM_BYTES (EPI_OFF + BM * EPITCH)   // 110592 + 67584 = 178176
#define GRID_GEMM 152
#define NTILES (NS * (PD / BM) * (PD / BN))       // 1024

__device__ __forceinline__ void gemm_load_stage(
    uint32_t sb, int stage, int kc, int tid,
    const uint8_t* Asrc, const uint8_t* Bsrc) {
    uint32_t base = sb + stage * STG;
    #pragma unroll
    for (int i = 0; i < 2; i++) {               // A: 128 rows x 8 chunks = 1024
        int id = tid + i * 512;
        int row = id >> 3, g = id & 7;
        CP_ASYNC16(base + row * PITCH + g * 16, Asrc + (size_t)row * CD + kc * 128 + g * 16);
    }
    #pragma unroll
    for (int i = 0; i < 4; i++) {               // B: 256 rows x 8 chunks = 2048
        int id = tid + i * 512;
        int row = id >> 3, g = id & 7;
        CP_ASYNC16(base + ASZ + row * PITCH + g * 16, Bsrc + (size_t)row * CD + kc * 128 + g * 16);
    }
}

__device__ __forceinline__ void gemm_compute_chunk(uint32_t aB, uint32_t bB, float d[2][8][4]) {
    #pragma unroll
    for (int kk = 0; kk < 4; kk++) {   // 4 x k32 (32 bytes each)
        uint32_t a[2][4], b[4][4];
        LDSM_X4(a[0], aB + kk * 32);
        LDSM_X4(a[1], aB + 16 * PITCH + kk * 32);
        #pragma unroll
        for (int nb = 0; nb < 4; nb++)
            LDSM_X4(b[nb], bB + nb * 16 * PITCH + kk * 32);
        #pragma unroll
        for (int mi = 0; mi < 2; mi++)
            #pragma unroll
            for (int ni = 0; ni < 8; ni++) {
                uint32_t* bp = b[ni >> 1];
                MMA_FP8(d[mi][ni], a[mi], bp[(ni & 1) * 2], bp[(ni & 1) * 2 + 1]);
            }
    }
}

__device__ __forceinline__ void gemm_decode(int t, const uint8_t** A, const uint8_t** B,
                                            int* n2, int* pt0, int* pi0) {
    *n2 = t >> 9;                 // 512 tiles per sample
    int rem = t & 511;
    *pt0 = (rem >> 4) * BM;       // 32 pt tiles
    *pi0 = (rem & 15) * BN;       // 16 pi tiles
    *A = g_Tn + ((size_t)(*n2) * PD + *pt0) * CD;
    *B = g_In + ((size_t)(*n2) * PD + *pi0) * CD;
}

__global__ void __launch_bounds__(512, 1) k_gemm() {
    extern __shared__ char smem[];
    uint32_t sb = smem_to_u32(smem);
    int tid = threadIdx.x, lane = tid & 31, wid = tid >> 5;

    int m0 = (wid & 3) * 32;        // 4 M-warps x 32 rows
    int n0 = (wid >> 2) * 64;       // 4 N-warps x 64 cols
    uint32_t aOff = (uint32_t)((m0 + (lane & 15)) * PITCH + (lane >> 4) * 16);
    uint32_t bOff = (uint32_t)(ASZ + (n0 + (lane & 7) + ((lane >> 4) * 8)) * PITCH
                               + ((lane >> 3) & 1) * 16);
    int gID = lane >> 2, tig = lane & 3;
    const float RS = 1.0f / 256.0f;   // undo the x16*x16 feature scaling

    int t = blockIdx.x;
    if (t >= NTILES) return;
    const uint8_t *Asrc, *Bsrc;
    int n2, pt0, pi0;
    gemm_decode(t, &Asrc, &Bsrc, &n2, &pt0, &pi0);

    gemm_load_stage(sb, 0, 0, tid, Asrc, Bsrc); CP_COMMIT();
    gemm_load_stage(sb, 1, 1, tid, Asrc, Bsrc); CP_COMMIT();

    while (true) {
        int tn = t + GRID_GEMM;
        bool more = (tn < NTILES);
        const uint8_t *An = nullptr, *Bn = nullptr;
        int nn2, npt0, npi0;
        if (more) gemm_decode(tn, &An, &Bn, &nn2, &npt0, &npi0);

        float d[2][8][4] = {};

        CP_WAIT(1); __syncthreads();
        gemm_compute_chunk(sb + aOff, sb + bOff, d);
        __syncthreads();
        if (more) { gemm_load_stage(sb, 0, 0, tid, An, Bn); CP_COMMIT(); }

        CP_WAIT(1); __syncthreads();
        gemm_compute_chunk(sb + STG + aOff, sb + STG + bOff, d);
        __syncthreads();
        if (more) { gemm_load_stage(sb, 1, 1, tid, An, Bn); CP_COMMIT(); }

        // ---- epilogue (separate smem buffer; overlaps with next tile's cp.async) ----
        char* epi = smem + EPI_OFF;
        #pragma unroll
        for (int ni = 0; ni < 8; ni++) {
            float mx0 = -2.0f, mx1 = -2.0f;
            int col = n0 + ni * 8 + tig * 2;
            #pragma unroll
            for (int mi = 0; mi < 2; mi++) {
                float* dd = d[mi][ni];
                __half2 h01 = __floats2half2_rn(dd[0] * RS, dd[1] * RS);
                __half2 h23 = __floats2half2_rn(dd[2] * RS, dd[3] * RS);
                int row = m0 + mi * 16 + gID;
                *(__half2*)(epi + row * EPITCH + col * 2) = h01;
                *(__half2*)(epi + (row + 8) * EPITCH + col * 2) = h23;
                mx0 = fmaxf(mx0, fmaxf(__low2float(h01), __low2float(h23)));
                mx1 = fmaxf(mx1, fmaxf(__high2float(h01), __high2float(h23)));
            }
            #pragma unroll
            for (int o = 4; o < 32; o <<= 1) {
                mx0 = fmaxf(mx0, __shfl_xor_sync(0xffffffffu, mx0, o));
                mx1 = fmaxf(mx1, __shfl_xor_sync(0xffffffffu, mx1, o));
            }
            if (lane < 4 && tig == lane) {
                int pi = pi0 + col;
                atomicMin((int*)&g_colmin[(size_t)n2 * PD + pi],
                          __float_as_int(0.5f - 0.5f * mx0));
                atomicMin((int*)&g_colmin[(size_t)n2 * PD + pi + 1],
                          __float_as_int(0.5f - 0.5f * mx1));
            }
        }
        __syncthreads();
        #pragma unroll
        for (int it = 0; it < 8; it++) {
            int idx = it * 512 + tid;          // 4096 = 128 rows x 32 uint4
            int r = idx >> 5, q = idx & 31;
            uint4 v = *(uint4*)(epi + r * EPITCH + q * 16);
            *(uint4*)(g_dot + ((size_t)n2 * PD + pt0 + r) * PD + pi0 + q * 8) = v;
        }

        if (!more) break;
        t = tn; Asrc = An; Bsrc = Bn; n2 = nn2; pt0 = npt0; pi0 = npi0;
        __syncthreads();   // epi buffer fully read before next tile's staging
    }
}

// ---------------- kernel 4: column sums S[n][pi] = sum_pt exp(c1*(dot-dmax)) ----------------
// 8 columns per thread via uint4 loads; MUFU ex2: exp(c1*(d-dmax)) = ex2(c2*d + bias)
#define SC_ROWS 32
__global__ void __launch_bounds__(256) k_sumcols() {
    int n = blockIdx.z;
    int pi = blockIdx.x * 2048 + threadIdx.x * 8;
    int pt0 = blockIdx.y * SC_ROWS;
    float c2[8], bs[8], sum[8];
    float4 m0 = *(float4*)&g_colmin[(size_t)n * PD + pi];
    float4 m1 = *(float4*)&g_colmin[(size_t)n * PD + pi + 4];
    float mns[8] = {m0.x, m0.y, m0.z, m0.w, m1.x, m1.y, m1.z, m1.w};
    #pragma unroll
    for (int j = 0; j < 8; j++) {
        c2[j] = (5.0f * LOG2E) / (mns[j] + EPSF);
        bs[j] = -c2[j] * (1.0f - 2.0f * mns[j]);
        sum[j] = 0.0f;
    }
    const uint4* base = (const uint4*)(g_dot + ((size_t)n * PD + pt0) * PD + pi);
    #pragma unroll 4
    for (int r = 0; r < SC_ROWS; r++) {
        uint4 v = base[(size_t)r * (PD / 8)];
        __half2 h[4] = {*(__half2*)&v.x, *(__half2*)&v.y, *(__half2*)&v.z, *(__half2*)&v.w};
        #pragma unroll
        for (int q = 0; q < 4; q++) {
            float2 f = __half22float2(h[q]);
            sum[q * 2 + 0] += ex2(fmaf(f.x, c2[q * 2 + 0], bs[q * 2 + 0]));
            sum[q * 2 + 1] += ex2(fmaf(f.y, c2[q * 2 + 1], bs[q * 2 + 1]));
        }
    }
    #pragma unroll
    for (int j = 0; j < 8; j++)
        atomicAdd(&g_S[(size_t)n * PD + pi + j], sum[j]);
}

// ---------------- kernel 5: final scalar ----------------
// cx_sp is exactly the identity in fp32 (off-diagonal exponents <= -225 underflow),
// so m[pt] = 0.5 * (1 + cx_feat[pt][pt]) and only the dot diagonal is needed.
__global__ void k_final(float* __restrict__ out) {
    __shared__ float sh[256];
    __shared__ float lossn[NS];
    int tid = threadIdx.x;
    for (int n = 0; n < NS; n++) {
        float s = 0.0f;
        for (int p = tid; p < PD; p += 256) {
            float mn = g_colmin[(size_t)n * PD + p];
            float c1 = 5.0f / (mn + EPSF);
            float dmax = 1.0f - 2.0f * mn;
            float dd = __half2float(g_dot[((size_t)n * PD + p) * PD + p]);
            float cxf = fexp(c1 * (dd - dmax)) / g_S[(size_t)n * PD + p];
            s += 0.5f + 0.5f * cxf;
        }
        sh[tid] = s; __syncthreads();
        for (int o = 128; o > 0; o >>= 1) { if (tid < o) sh[tid] += sh[tid + o]; __syncthreads(); }
        if (tid == 0) lossn[n] = -logf(sh[0] * (1.0f / (float)PD));
        __syncthreads();
    }
    if (tid == 0) {
        float acc = 0.0f;
        for (int n = 0; n < NS; n++) acc += lossn[n];
        out[0] = acc * (1.0f / (float)NS);
    }
}

// ---------------- launch ----------------
extern "C" void kernel_launch(void* const* d_in, const int* in_sizes, int n_in,
                              void* d_out, int out_size) {
    const float* I = (const float*)d_in[0];
    const float* T = (const float*)d_in[1];
    float* out = (float*)d_out;

    cudaFuncSetAttribute(k_gemm, cudaFuncAttributeMaxDynamicSharedMemorySize, GEMM_SMEM_BYTES);

    k_mean<<<CD, 256>>>(T);
    k_norm2<<<dim3(PD / NP, NS, 2), 256>>>(I, T);
    k_gemm<<<GRID_GEMM, 512, GEMM_SMEM_BYTES>>>();
    k_sumcols<<<dim3(PD / 2048, PD / SC_ROWS, NS), 256>>>();
    k_final<<<1, 256>>>(out);
}

// round 6
// speedup vs baseline: 1.0707x; 1.0707x over previous
#include <cuda_runtime.h>
#include <cuda_fp16.h>
#include <cuda_bf16.h>
#include <cstdint>

// ---------------- problem constants ----------------
#define NS 2
#define CD 256
#define PD 4096            // 64*64
#define EPSF 1e-5f
#define LOG2E 1.4426950408889634f

// ---------------- device scratch (no runtime allocs allowed) ----------------
static __device__ __half   g_dot[(size_t)NS * PD * PD];   // 64 MiB: dot[n][pt][pi]
static __device__ uint8_t  g_Tn[(size_t)NS * PD * CD];    // normalized T, fp8 e4m3 x16, [n][p][c]
static __device__ uint8_t  g_In[(size_t)NS * PD * CD];    // normalized I, fp8 e4m3 x16, [n][p][c]
static __device__ float g_meanT[CD];
static __device__ float g_colmin[NS * PD];   // min over pt of raw=(1-dot)/2 per (n,pi); >=0
static __device__ float g_S[NS * PD];        // sum_pt exp(c1*(dot-dmax)) per (n,pi)

// ---------------- asm helpers (baseline sm_80/sm_89 ISA only) ----------------
__device__ __forceinline__ uint32_t smem_to_u32(const void* p) {
    uint32_t a;
    asm("{ .reg .u64 t; cvta.to.shared.u64 t, %1; cvt.u32.u64 %0, t; }" : "=r"(a) : "l"(p));
    return a;
}
#define CP_ASYNC16(dst, src) \
    asm volatile("cp.async.cg.shared.global [%0], [%1], 16;" :: "r"(dst), "l"(src) : "memory")
#define CP_COMMIT() asm volatile("cp.async.commit_group;" ::: "memory")
#define CP_WAIT(N)  asm volatile("cp.async.wait_group %0;" :: "n"(N) : "memory")
#define NAMED_BAR(id) asm volatile("bar.sync %0, 128;" :: "r"(id) : "memory")

#define LDSM_X4(R, addr) \
    asm volatile("ldmatrix.sync.aligned.m8n8.x4.shared.b16 {%0,%1,%2,%3}, [%4];" \
        : "=r"((R)[0]), "=r"((R)[1]), "=r"((R)[2]), "=r"((R)[3]) : "r"(addr))

// fp8 e4m3 MMA: m16n8k32, A row-major (K-major), B col-major (K-major), f32 accum
#define MMA_FP8(D, A, B0, B1) \
    asm volatile("mma.sync.aligned.m16n8k32.row.col.f32.e4m3.e4m3.f32 " \
        "{%0,%1,%2,%3}, {%4,%5,%6,%7}, {%8,%9}, {%0,%1,%2,%3};" \
        : "+f"((D)[0]), "+f"((D)[1]), "+f"((D)[2]), "+f"((D)[3]) \
        : "r"((A)[0]), "r"((A)[1]), "r"((A)[2]), "r"((A)[3]), "r"(B0), "r"(B1))

// pack two floats -> e4m3x2 (lo = first elem, hi = second elem)
__device__ __forceinline__ uint16_t pack_e4m3(float lo, float hi) {
    uint16_t r;
    asm("cvt.rn.satfinite.e4m3x2.f32 %0, %1, %2;" : "=h"(r) : "f"(hi), "f"(lo));
    return r;
}
__device__ __forceinline__ float ex2(float x) {
    float r;
    asm("ex2.approx.ftz.f32 %0, %1;" : "=f"(r) : "f"(x));
    return r;
}
__device__ __forceinline__ float fexp(float x) {
    return ex2(fmaxf(x, -120.0f) * LOG2E);
}

// ---------------- kernel 1: meanT per channel (+ fused accumulator init) ----------------
__global__ void k_mean(const float* __restrict__ T) {
    int c = blockIdx.x;       // 256
    int tid = threadIdx.x;    // 256
    if (tid < 32) {           // 256 blocks x 32 = 8192 = NS*PD
        int i = c * 32 + tid;
        g_colmin[i] = 3.402823466e38f;
        g_S[i] = 0.0f;
    }
    float s = 0.0f;
    #pragma unroll
    for (int n = 0; n < NS; n++) {
        const float4* b4 = (const float4*)(T + ((size_t)n * CD + c) * PD);
        #pragma unroll
        for (int i = tid; i < PD / 4; i += 256) {
            float4 v = b4[i];
            s += v.x + v.y + v.z + v.w;
        }
    }
    __shared__ float sh[256];
    sh[tid] = s; __syncthreads();
    for (int o = 128; o > 0; o >>= 1) { if (tid < o) sh[tid] += sh[tid + o]; __syncthreads(); }
    if (tid == 0) g_meanT[c] = sh[0] * (1.0f / (float)(NS * PD));
}

// ---------------- kernel 2: center + normalize(+x16) + transpose -> fp8 ----------------
#define NP 32
#define BPITCH 260   // floats per p-row (256 + 4 pad)
__global__ void __launch_bounds__(256) k_norm2(const float* __restrict__ I,
                                               const float* __restrict__ T) {
    const float* X = blockIdx.z ? I : T;
    uint8_t* out = blockIdx.z ? g_In : g_Tn;
    int n = blockIdx.y;
    int p0 = blockIdx.x * NP;
    int tid = threadIdx.x;
    __shared__ float buf[NP][BPITCH];   // [p][c]
    __shared__ float nrm[8][NP];

    const float* base = X + (size_t)n * CD * PD + p0;
    #pragma unroll
    for (int it = 0; it < 8; it++) {
        int idx = it * 256 + tid;       // 2048 = 256 c * 8 float4
        int c = idx >> 3, j = idx & 7;
        float4 v = *(const float4*)(base + (size_t)c * PD + j * 4);
        float mc = g_meanT[c];
        buf[j * 4 + 0][c] = v.x - mc;
        buf[j * 4 + 1][c] = v.y - mc;
        buf[j * 4 + 2][c] = v.z - mc;
        buf[j * 4 + 3][c] = v.w - mc;
    }
    __syncthreads();
    {
        int p = tid >> 3, k = tid & 7;  // 32 p x 8 chunks
        float s = 0.0f;
        #pragma unroll
        for (int m = 0; m < 32; m++) { float v = buf[p][k * 32 + m]; s += v * v; }
        nrm[k][p] = s;
    }
    __syncthreads();
    if (tid < NP) {
        float t = 0.0f;
        #pragma unroll
        for (int k = 0; k < 8; k++) t += nrm[k][tid];
        nrm[0][tid] = rsqrtf(t) * 16.0f;   // x16 scale: e4m3 values ~O(1)
    }
    __syncthreads();
    uint8_t* ob = out + ((size_t)n * PD + p0) * CD;
    #pragma unroll
    for (int it = 0; it < 4; it++) {
        int idx = it * 256 + tid;       // 1024 = 32 p * 32 8-byte groups
        int p = idx >> 5, q = idx & 31;
        float sc = nrm[0][p];
        float4 v0 = *(float4*)&buf[p][q * 8];
        float4 v1 = *(float4*)&buf[p][q * 8 + 4];
        uint16_t h0 = pack_e4m3(v0.x * sc, v0.y * sc);
        uint16_t h1 = pack_e4m3(v0.z * sc, v0.w * sc);
        uint16_t h2 = pack_e4m3(v1.x * sc, v1.y * sc);
        uint16_t h3 = pack_e4m3(v1.z * sc, v1.w * sc);
        uint2 u;
        u.x = (uint32_t)h0 | ((uint32_t)h1 << 16);
        u.y = (uint32_t)h2 | ((uint32_t)h3 << 16);
        *(uint2*)(ob + (size_t)p * CD + q * 8) = u;
    }
}

// ---------------- kernel 3: persistent fp8 MMA GEMM, 128x256 tiles, cross-tile pipeline ----------------
#define BM 128
#define BN 256
#define PITCH 144                 // 128 fp8 bytes + 16B pad
#define ASZ (BM * PITCH)          // 18432
#define BSZ (BN * PITCH)          // 36864
#define STG (ASZ + BSZ)           // 55296
#define EPI_OFF (2 * STG)         // 110592
#define EPITCH 528                // epilogue fp16 row pitch (256*2 + 16)
#define GEMM_SMEM_BYTES (EPI_OFF + BM * EPITCH)   // 110592 + 67584 = 178176
#define GRID_GEMM 152
#define NTILES (NS * (PD / BM) * (PD / BN))       // 1024

__device__ __forceinline__ void gemm_load_stage(
    uint32_t sb, int stage, int kc, int tid,
    const uint8_t* Asrc, const uint8_t* Bsrc) {
    uint32_t base = sb + stage * STG;
    #pragma unroll
    for (int i = 0; i < 2; i++) {               // A: 128 rows x 8 chunks = 1024
        int id = tid + i * 512;
        int row = id >> 3, g = id & 7;
        CP_ASYNC16(base + row * PITCH + g * 16, Asrc + (size_t)row * CD + kc * 128 + g * 16);
    }
    #pragma unroll
    for (int i = 0; i < 4; i++) {               // B: 256 rows x 8 chunks = 2048
        int id = tid + i * 512;
        int row = id >> 3, g = id & 7;
        CP_ASYNC16(base + ASZ + row * PITCH + g * 16, Bsrc + (size_t)row * CD + kc * 128 + g * 16);
    }
}

__device__ __forceinline__ void gemm_compute_chunk(uint32_t aB, uint32_t bB, float d[2][8][4]) {
    #pragma unroll
    for (int kk = 0; kk < 4; kk++) {   // 4 x k32 (32 bytes each)
        uint32_t a[2][4], b[4][4];
        LDSM_X4(a[0], aB + kk * 32);
        LDSM_X4(a[1], aB + 16 * PITCH + kk * 32);
        #pragma unroll
        for (int nb = 0; nb < 4; nb++)
            LDSM_X4(b[nb], bB + nb * 16 * PITCH + kk * 32);
        #pragma unroll
        for (int mi = 0; mi < 2; mi++)
            #pragma unroll
            for (int ni = 0; ni < 8; ni++) {
                uint32_t* bp = b[ni >> 1];
                MMA_FP8(d[mi][ni], a[mi], bp[(ni & 1) * 2], bp[(ni & 1) * 2 + 1]);
            }
    }
}

__device__ __forceinline__ void gemm_decode(int t, const uint8_t** A, const uint8_t** B,
                                            int* n2, int* pt0, int* pi0) {
    *n2 = t >> 9;                 // 512 tiles per sample
    int rem = t & 511;
    *pt0 = (rem >> 4) * BM;       // 32 pt tiles
    *pi0 = (rem & 15) * BN;       // 16 pi tiles
    *A = g_Tn + ((size_t)(*n2) * PD + *pt0) * CD;
    *B = g_In + ((size_t)(*n2) * PD + *pi0) * CD;
}

__global__ void __launch_bounds__(512, 1) k_gemm() {
    extern __shared__ char smem[];
    uint32_t sb = smem_to_u32(smem);
    int tid = threadIdx.x, lane = tid & 31, wid = tid >> 5;

    int mw = wid & 3;               // m-group: 4 warps (wid&3 equal) own rows m0..m0+31
    int m0 = mw * 32;
    int n0 = (wid >> 2) * 64;       // 4 N-warps x 64 cols
    uint32_t aOff = (uint32_t)((m0 + (lane & 15)) * PITCH + (lane >> 4) * 16);
    uint32_t bOff = (uint32_t)(ASZ + (n0 + (lane & 7) + ((lane >> 4) * 8)) * PITCH
                               + ((lane >> 3) & 1) * 16);
    int gID = lane >> 2, tig = lane & 3;
    int gtid = (wid >> 2) * 32 + lane;   // 0..127 within m-group
    const float RS = 1.0f / 256.0f;      // undo the x16*x16 feature scaling

    int t = blockIdx.x;
    if (t >= NTILES) return;
    const uint8_t *Asrc, *Bsrc;
    int n2, pt0, pi0;
    gemm_decode(t, &Asrc, &Bsrc, &n2, &pt0, &pi0);

    gemm_load_stage(sb, 0, 0, tid, Asrc, Bsrc); CP_COMMIT();
    gemm_load_stage(sb, 1, 1, tid, Asrc, Bsrc); CP_COMMIT();

    while (true) {
        int tn = t + GRID_GEMM;
        bool more = (tn < NTILES);
        const uint8_t *An = nullptr, *Bn = nullptr;
        int nn2, npt0, npi0;
        if (more) gemm_decode(tn, &An, &Bn, &nn2, &npt0, &npi0);

        float d[2][8][4] = {};

        CP_WAIT(1); __syncthreads();
        gemm_compute_chunk(sb + aOff, sb + bOff, d);
        __syncthreads();
        if (more) { gemm_load_stage(sb, 0, 0, tid, An, Bn); CP_COMMIT(); }

        CP_WAIT(1); __syncthreads();
        gemm_compute_chunk(sb + STG + aOff, sb + STG + bOff, d);
        __syncthreads();
        if (more) { gemm_load_stage(sb, 1, 1, tid, An, Bn); CP_COMMIT(); }

        // ---- epilogue: per-m-group (named barriers), overlaps other groups + next loads ----
        char* epi = smem + EPI_OFF;
        NAMED_BAR(1 + mw);   // group's previous-tile epi reads complete before overwrite
        #pragma unroll
        for (int ni = 0; ni < 8; ni++) {
            float mx0 = -2.0f, mx1 = -2.0f;
            int col = n0 + ni * 8 + tig * 2;
            #pragma unroll
            for (int mi = 0; mi < 2; mi++) {
                float* dd = d[mi][ni];
                __half2 h01 = __floats2half2_rn(dd[0] * RS, dd[1] * RS);
                __half2 h23 = __floats2half2_rn(dd[2] * RS, dd[3] * RS);
                int row = m0 + mi * 16 + gID;
                *(__half2*)(epi + row * EPITCH + col * 2) = h01;
                *(__half2*)(epi + (row + 8) * EPITCH + col * 2) = h23;
                mx0 = fmaxf(mx0, fmaxf(__low2float(h01), __low2float(h23)));
                mx1 = fmaxf(mx1, fmaxf(__high2float(h01), __high2float(h23)));
            }
            #pragma unroll
            for (int o = 4; o < 32; o <<= 1) {
                mx0 = fmaxf(mx0, __shfl_xor_sync(0xffffffffu, mx0, o));
                mx1 = fmaxf(mx1, __shfl_xor_sync(0xffffffffu, mx1, o));
            }
            if (lane < 4 && tig == lane) {
                int pi = pi0 + col;
                atomicMin((int*)&g_colmin[(size_t)n2 * PD + pi],
                          __float_as_int(0.5f - 0.5f * mx0));
                atomicMin((int*)&g_colmin[(size_t)n2 * PD + pi + 1],
                          __float_as_int(0.5f - 0.5f * mx1));
            }
        }
        NAMED_BAR(1 + mw);   // group's epi rows fully written
        #pragma unroll
        for (int it = 0; it < 8; it++) {
            int idx = it * 128 + gtid;          // 1024 = 32 rows x 32 uint4
            int r = m0 + (idx >> 5), q = idx & 31;
            uint4 v = *(uint4*)(epi + r * EPITCH + q * 16);
            *(uint4*)(g_dot + ((size_t)n2 * PD + pt0 + r) * PD + pi0 + q * 8) = v;
        }

        if (!more) break;
        t = tn; Asrc = An; Bsrc = Bn; n2 = nn2; pt0 = npt0; pi0 = npi0;
    }
}

// ---------------- kernel 4: column sums S[n][pi] = sum_pt exp(c1*(dot-dmax)) ----------------
// MUFU ex2 path: exp(c1*(d-dmax)) = ex2(c2*d + bias). Blocks traverse in reverse
// GEMM-write order (sample 1 / high pt first) to catch still-L2-resident dot rows.
__global__ void __launch_bounds__(256) k_sumcols() {
    int n = (NS - 1) - (int)blockIdx.z;
    int pi = (blockIdx.x * 256 + threadIdx.x) * 2;
    int pt0 = PD - 256 - (int)blockIdx.y * 256;
    float2 mn2 = *(float2*)&g_colmin[(size_t)n * PD + pi];
    float c2a = (5.0f * LOG2E) / (mn2.x + EPSF), c2b = (5.0f * LOG2E) / (mn2.y + EPSF);
    float ba = -c2a * (1.0f - 2.0f * mn2.x);   // -c2*dmax
    float bb = -c2b * (1.0f - 2.0f * mn2.y);
    const __half2* col = (const __half2*)(g_dot + ((size_t)n * PD + pt0) * PD + pi);
    float sa = 0.0f, sb = 0.0f;
    #pragma unroll 16
    for (int r = 0; r < 256; r++) {
        float2 f = __half22float2(col[(size_t)r * (PD / 2)]);
        sa += ex2(fmaf(f.x, c2a, ba));
        sb += ex2(fmaf(f.y, c2b, bb));
    }
    atomicAdd(&g_S[(size_t)n * PD + pi], sa);
    atomicAdd(&g_S[(size_t)n * PD + pi + 1], sb);
}

// ---------------- kernel 5: final scalar ----------------
// cx_sp is exactly the identity in fp32 (off-diagonal exponents <= -225 underflow),
// so m[pt] = 0.5 * (1 + cx_feat[pt][pt]) and only the dot diagonal is needed.
__global__ void k_final(float* __restrict__ out) {
    __shared__ float sh[256];
    __shared__ float lossn[NS];
    int tid = threadIdx.x;
    for (int n = 0; n < NS; n++) {
        float s = 0.0f;
        for (int p = tid; p < PD; p += 256) {
            float mn = g_colmin[(size_t)n * PD + p];
            float c1 = 5.0f / (mn + EPSF);
            float dmax = 1.0f - 2.0f * mn;
            float dd = __half2float(g_dot[((size_t)n * PD + p) * PD + p]);
            float cxf = fexp(c1 * (dd - dmax)) / g_S[(size_t)n * PD + p];
            s += 0.5f + 0.5f * cxf;
        }
        sh[tid] = s; __syncthreads();
        for (int o = 128; o > 0; o >>= 1) { if (tid < o) sh[tid] += sh[tid + o]; __syncthreads(); }
        if (tid == 0) lossn[n] = -logf(sh[0] * (1.0f / (float)PD));
        __syncthreads();
    }
    if (tid == 0) {
        float acc = 0.0f;
        for (int n = 0; n < NS; n++) acc += lossn[n];
        out[0] = acc * (1.0f / (float)NS);
    }
}

// ---------------- launch ----------------
extern "C" void kernel_launch(void* const* d_in, const int* in_sizes, int n_in,
                              void* d_out, int out_size) {
    const float* I = (const float*)d_in[0];
    const float* T = (const float*)d_in[1];
    float* out = (float*)d_out;

    cudaFuncSetAttribute(k_gemm, cudaFuncAttributeMaxDynamicSharedMemorySize, GEMM_SMEM_BYTES);

    k_mean<<<CD, 256>>>(T);
    k_norm2<<<dim3(PD / NP, NS, 2), 256>>>(I, T);
    k_gemm<<<GRID_GEMM, 512, GEMM_SMEM_BYTES>>>();
    k_sumcols<<<dim3(PD / 512, PD / 256, NS), 256>>>();
    k_final<<<1, 256>>>(out);
}

// round 7
// speedup vs baseline: 1.1267x; 1.0523x over previous
#include <cuda_runtime.h>
#include <cuda_fp16.h>
#include <cuda_bf16.h>
#include <cstdint>

// ---------------- problem constants ----------------
#define NS 2
#define CD 256
#define PD 4096            // 64*64
#define EPSF 1e-5f
#define LOG2E 1.4426950408889634f

// ---------------- device scratch (no runtime allocs allowed) ----------------
static __device__ __half   g_dot[(size_t)NS * PD * PD];   // 64 MiB: dot[n][pt][pi]
static __device__ uint8_t  g_Tn[(size_t)NS * PD * CD];    // normalized T, fp8 e4m3 x16, [n][p][c]
static __device__ uint8_t  g_In[(size_t)NS * PD * CD];    // normalized I, fp8 e4m3 x16, [n][p][c]
static __device__ float g_meanT[CD];
static __device__ float g_colmin[NS * PD];   // min over pt of raw=(1-dot)/2 per (n,pi); >=0
static __device__ float g_S[NS * PD];        // sum_pt exp(c1*(dot-dmax)) per (n,pi)

// ---------------- asm helpers (baseline sm_80/sm_89 ISA only) ----------------
__device__ __forceinline__ uint32_t smem_to_u32(const void* p) {
    uint32_t a;
    asm("{ .reg .u64 t; cvta.to.shared.u64 t, %1; cvt.u32.u64 %0, t; }" : "=r"(a) : "l"(p));
    return a;
}
#define CP_ASYNC16(dst, src) \
    asm volatile("cp.async.cg.shared.global [%0], [%1], 16;" :: "r"(dst), "l"(src) : "memory")
#define CP_COMMIT() asm volatile("cp.async.commit_group;" ::: "memory")
#define CP_WAIT(N)  asm volatile("cp.async.wait_group %0;" :: "n"(N) : "memory")
#define NAMED_BAR(id) asm volatile("bar.sync %0, 128;" :: "r"(id) : "memory")

#define LDSM_X4(R, addr) \
    asm volatile("ldmatrix.sync.aligned.m8n8.x4.shared.b16 {%0,%1,%2,%3}, [%4];" \
        : "=r"((R)[0]), "=r"((R)[1]), "=r"((R)[2]), "=r"((R)[3]) : "r"(addr))

// fp8 e4m3 MMA: m16n8k32, A row-major (K-major), B col-major (K-major), f32 accum
#define MMA_FP8(D, A, B0, B1) \
    asm volatile("mma.sync.aligned.m16n8k32.row.col.f32.e4m3.e4m3.f32 " \
        "{%0,%1,%2,%3}, {%4,%5,%6,%7}, {%8,%9}, {%0,%1,%2,%3};" \
        : "+f"((D)[0]), "+f"((D)[1]), "+f"((D)[2]), "+f"((D)[3]) \
        : "r"((A)[0]), "r"((A)[1]), "r"((A)[2]), "r"((A)[3]), "r"(B0), "r"(B1))

// pack two floats -> e4m3x2 (lo = first elem, hi = second elem)
__device__ __forceinline__ uint16_t pack_e4m3(float lo, float hi) {
    uint16_t r;
    asm("cvt.rn.satfinite.e4m3x2.f32 %0, %1, %2;" : "=h"(r) : "f"(hi), "f"(lo));
    return r;
}
__device__ __forceinline__ float ex2(float x) {
    float r;
    asm("ex2.approx.ftz.f32 %0, %1;" : "=f"(r) : "f"(x));
    return r;
}
__device__ __forceinline__ float fexp(float x) {
    return ex2(fmaxf(x, -120.0f) * LOG2E);
}

// ---------------- kernel 1: meanT per channel (+ fused accumulator init) ----------------
__global__ void k_mean(const float* __restrict__ T) {
    int c = blockIdx.x;       // 256
    int tid = threadIdx.x;    // 256
    if (tid < 32) {           // 256 blocks x 32 = 8192 = NS*PD
        int i = c * 32 + tid;
        g_colmin[i] = 3.402823466e38f;
        g_S[i] = 0.0f;
    }
    float s = 0.0f;
    #pragma unroll
    for (int n = 0; n < NS; n++) {
        const float4* b4 = (const float4*)(T + ((size_t)n * CD + c) * PD);
        #pragma unroll
        for (int i = tid; i < PD / 4; i += 256) {
            float4 v = b4[i];
            s += v.x + v.y + v.z + v.w;
        }
    }
    __shared__ float sh[256];
    sh[tid] = s; __syncthreads();
    for (int o = 128; o > 0; o >>= 1) { if (tid < o) sh[tid] += sh[tid + o]; __syncthreads(); }
    if (tid == 0) g_meanT[c] = sh[0] * (1.0f / (float)(NS * PD));
}

// ---------------- kernel 2: center + normalize(+x16) + transpose -> fp8 ----------------
#define NP 32
#define BPITCH 260   // floats per p-row (256 + 4 pad)
__global__ void __launch_bounds__(256) k_norm2(const float* __restrict__ I,
                                               const float* __restrict__ T) {
    const float* X = blockIdx.z ? I : T;
    uint8_t* out = blockIdx.z ? g_In : g_Tn;
    int n = blockIdx.y;
    int p0 = blockIdx.x * NP;
    int tid = threadIdx.x;
    __shared__ float buf[NP][BPITCH];   // [p][c]
    __shared__ float nrm[8][NP];

    const float* base = X + (size_t)n * CD * PD + p0;
    #pragma unroll
    for (int it = 0; it < 8; it++) {
        int idx = it * 256 + tid;       // 2048 = 256 c * 8 float4
        int c = idx >> 3, j = idx & 7;
        float4 v = *(const float4*)(base + (size_t)c * PD + j * 4);
        float mc = g_meanT[c];
        buf[j * 4 + 0][c] = v.x - mc;
        buf[j * 4 + 1][c] = v.y - mc;
        buf[j * 4 + 2][c] = v.z - mc;
        buf[j * 4 + 3][c] = v.w - mc;
    }
    __syncthreads();
    {
        int p = tid >> 3, k = tid & 7;  // 32 p x 8 chunks
        float s = 0.0f;
        #pragma unroll
        for (int m = 0; m < 32; m++) { float v = buf[p][k * 32 + m]; s += v * v; }
        nrm[k][p] = s;
    }
    __syncthreads();
    if (tid < NP) {
        float t = 0.0f;
        #pragma unroll
        for (int k = 0; k < 8; k++) t += nrm[k][tid];
        nrm[0][tid] = rsqrtf(t) * 16.0f;   // x16 scale: e4m3 values ~O(1)
    }
    __syncthreads();
    uint8_t* ob = out + ((size_t)n * PD + p0) * CD;
    #pragma unroll
    for (int it = 0; it < 4; it++) {
        int idx = it * 256 + tid;       // 1024 = 32 p * 32 8-byte groups
        int p = idx >> 5, q = idx & 31;
        float sc = nrm[0][p];
        float4 v0 = *(float4*)&buf[p][q * 8];
        float4 v1 = *(float4*)&buf[p][q * 8 + 4];
        uint16_t h0 = pack_e4m3(v0.x * sc, v0.y * sc);
        uint16_t h1 = pack_e4m3(v0.z * sc, v0.w * sc);
        uint16_t h2 = pack_e4m3(v1.x * sc, v1.y * sc);
        uint16_t h3 = pack_e4m3(v1.z * sc, v1.w * sc);
        uint2 u;
        u.x = (uint32_t)h0 | ((uint32_t)h1 << 16);
        u.y = (uint32_t)h2 | ((uint32_t)h3 << 16);
        *(uint2*)(ob + (size_t)p * CD + q * 8) = u;
    }
}

// ---------------- kernel 3: persistent fp8 MMA GEMM, 128x256 tiles, cross-tile pipeline ----------------
#define BM 128
#define BN 256
#define PITCH 144                 // 128 fp8 bytes + 16B pad
#define ASZ (BM * PITCH)          // 18432
#define BSZ (BN * PITCH)          // 36864
#define STG (ASZ + BSZ)           // 55296
#define EPI_OFF (2 * STG)         // 110592
#define EPITCH 528                // epilogue fp16 row pitch (256*2 + 16)
#define GEMM_SMEM_BYTES (EPI_OFF + BM * EPITCH)   // 110592 + 67584 = 178176
#define GRID_GEMM 152
#define NTILES (NS * (PD / BM) * (PD / BN))       // 1024

__device__ __forceinline__ void gemm_load_stage(
    uint32_t sb, int stage, int kc, int tid,
    const uint8_t* Asrc, const uint8_t* Bsrc) {
    uint32_t base = sb + stage * STG;
    #pragma unroll
    for (int i = 0; i < 2; i++) {               // A: 128 rows x 8 chunks = 1024
        int id = tid + i * 512;
        int row = id >> 3, g = id & 7;
        CP_ASYNC16(base + row * PITCH + g * 16, Asrc + (size_t)row * CD + kc * 128 + g * 16);
    }
    #pragma unroll
    for (int i = 0; i < 4; i++) {               // B: 256 rows x 8 chunks = 2048
        int id = tid + i * 512;
        int row = id >> 3, g = id & 7;
        CP_ASYNC16(base + ASZ + row * PITCH + g * 16, Bsrc + (size_t)row * CD + kc * 128 + g * 16);
    }
}

__device__ __forceinline__ void gemm_compute_chunk(uint32_t aB, uint32_t bB, float d[2][8][4]) {
    #pragma unroll
    for (int kk = 0; kk < 4; kk++) {   // 4 x k32 (32 bytes each)
        uint32_t a[2][4], b[4][4];
        LDSM_X4(a[0], aB + kk * 32);
        LDSM_X4(a[1], aB + 16 * PITCH + kk * 32);
        #pragma unroll
        for (int nb = 0; nb < 4; nb++)
            LDSM_X4(b[nb], bB + nb * 16 * PITCH + kk * 32);
        #pragma unroll
        for (int mi = 0; mi < 2; mi++)
            #pragma unroll
            for (int ni = 0; ni < 8; ni++) {
                uint32_t* bp = b[ni >> 1];
                MMA_FP8(d[mi][ni], a[mi], bp[(ni & 1) * 2], bp[(ni & 1) * 2 + 1]);
            }
    }
}

__device__ __forceinline__ void gemm_decode(int t, const uint8_t** A, const uint8_t** B,
                                            int* n2, int* pt0, int* pi0) {
    *n2 = t >> 9;                 // 512 tiles per sample
    int rem = t & 511;
    *pt0 = (rem >> 4) * BM;       // 32 pt tiles
    *pi0 = (rem & 15) * BN;       // 16 pi tiles
    *A = g_Tn + ((size_t)(*n2) * PD + *pt0) * CD;
    *B = g_In + ((size_t)(*n2) * PD + *pi0) * CD;
}

__global__ void __launch_bounds__(512, 1) k_gemm() {
    extern __shared__ char smem[];
    uint32_t sb = smem_to_u32(smem);
    int tid = threadIdx.x, lane = tid & 31, wid = tid >> 5;

    int mw = wid & 3;               // m-group: 4 warps (wid&3 equal) own rows m0..m0+31
    int m0 = mw * 32;
    int n0 = (wid >> 2) * 64;       // 4 N-warps x 64 cols
    uint32_t aOff = (uint32_t)((m0 + (lane & 15)) * PITCH + (lane >> 4) * 16);
    uint32_t bOff = (uint32_t)(ASZ + (n0 + (lane & 7) + ((lane >> 4) * 8)) * PITCH
                               + ((lane >> 3) & 1) * 16);
    int gID = lane >> 2, tig = lane & 3;
    int gtid = (wid >> 2) * 32 + lane;   // 0..127 within m-group
    const float RS = 1.0f / 256.0f;      // undo the x16*x16 feature scaling

    int t = blockIdx.x;
    if (t >= NTILES) return;
    const uint8_t *Asrc, *Bsrc;
    int n2, pt0, pi0;
    gemm_decode(t, &Asrc, &Bsrc, &n2, &pt0, &pi0);

    gemm_load_stage(sb, 0, 0, tid, Asrc, Bsrc); CP_COMMIT();
    gemm_load_stage(sb, 1, 1, tid, Asrc, Bsrc); CP_COMMIT();

    while (true) {
        int tn = t + GRID_GEMM;
        bool more = (tn < NTILES);
        const uint8_t *An = nullptr, *Bn = nullptr;
        int nn2, npt0, npi0;
        if (more) gemm_decode(tn, &An, &Bn, &nn2, &npt0, &npi0);

        float d[2][8][4] = {};

        CP_WAIT(1); __syncthreads();
        gemm_compute_chunk(sb + aOff, sb + bOff, d);
        __syncthreads();
        if (more) { gemm_load_stage(sb, 0, 0, tid, An, Bn); CP_COMMIT(); }

        CP_WAIT(1); __syncthreads();
        gemm_compute_chunk(sb + STG + aOff, sb + STG + bOff, d);
        __syncthreads();
        if (more) { gemm_load_stage(sb, 1, 1, tid, An, Bn); CP_COMMIT(); }

        // ---- epilogue: per-m-group (named barriers), overlaps other groups + next loads ----
        char* epi = smem + EPI_OFF;
        NAMED_BAR(1 + mw);   // group's previous-tile epi reads complete before overwrite
        #pragma unroll
        for (int ni = 0; ni < 8; ni++) {
            float mx0 = -2.0f, mx1 = -2.0f;
            int col = n0 + ni * 8 + tig * 2;
            #pragma unroll
            for (int mi = 0; mi < 2; mi++) {
                float* dd = d[mi][ni];
                __half2 h01 = __floats2half2_rn(dd[0] * RS, dd[1] * RS);
                __half2 h23 = __floats2half2_rn(dd[2] * RS, dd[3] * RS);
                int row = m0 + mi * 16 + gID;
                *(__half2*)(epi + row * EPITCH + col * 2) = h01;
                *(__half2*)(epi + (row + 8) * EPITCH + col * 2) = h23;
                mx0 = fmaxf(mx0, fmaxf(__low2float(h01), __low2float(h23)));
                mx1 = fmaxf(mx1, fmaxf(__high2float(h01), __high2float(h23)));
            }
            #pragma unroll
            for (int o = 4; o < 32; o <<= 1) {
                mx0 = fmaxf(mx0, __shfl_xor_sync(0xffffffffu, mx0, o));
                mx1 = fmaxf(mx1, __shfl_xor_sync(0xffffffffu, mx1, o));
            }
            if (lane < 4) {
                int pi = pi0 + col;
                atomicMin((int*)&g_colmin[(size_t)n2 * PD + pi],
                          __float_as_int(0.5f - 0.5f * mx0));
                atomicMin((int*)&g_colmin[(size_t)n2 * PD + pi + 1],
                          __float_as_int(0.5f - 0.5f * mx1));
            }
        }
        NAMED_BAR(1 + mw);   // group's epi rows fully written
        #pragma unroll
        for (int it = 0; it < 8; it++) {
            int idx = it * 128 + gtid;          // 1024 = 32 rows x 32 uint4
            int r = m0 + (idx >> 5), q = idx & 31;
            uint4 v = *(uint4*)(epi + r * EPITCH + q * 16);
            *(uint4*)(g_dot + ((size_t)n2 * PD + pt0 + r) * PD + pi0 + q * 8) = v;
        }

        if (!more) break;
        t = tn; Asrc = An; Bsrc = Bn; n2 = nn2; pt0 = npt0; pi0 = npi0;
    }
}

// ---------------- kernel 4: column sums S[n][pi] = sum_pt exp(c1*(dot-dmax)) ----------------
// R4-verified geometry: 1024 blocks (8 x 64 x 2), 64 rows/block, 2 cols/thread,
// unroll 16 (MLP ~16, DRAM-bound). MUFU ex2: exp(c1*(d-dmax)) = ex2(c2*d + bias).
// Reverse traversal (sample 1 / high pt first) catches the GEMM's freshest L2 lines.
__global__ void __launch_bounds__(256) k_sumcols() {
    int n = (NS - 1) - (int)blockIdx.z;
    int pi = (blockIdx.x * 256 + threadIdx.x) * 2;
    int pt0 = PD - 64 - (int)blockIdx.y * 64;
    float2 mn2 = *(float2*)&g_colmin[(size_t)n * PD + pi];
    float c2a = (5.0f * LOG2E) / (mn2.x + EPSF), c2b = (5.0f * LOG2E) / (mn2.y + EPSF);
    float ba = -c2a * (1.0f - 2.0f * mn2.x);   // -c2*dmax
    float bb = -c2b * (1.0f - 2.0f * mn2.y);
    const __half2* col = (const __half2*)(g_dot + ((size_t)n * PD + pt0) * PD + pi);
    float sa = 0.0f, sb = 0.0f;
    #pragma unroll 16
    for (int r = 0; r < 64; r++) {
        float2 f = __half22float2(col[(size_t)r * (PD / 2)]);
        sa += ex2(fmaf(f.x, c2a, ba));
        sb += ex2(fmaf(f.y, c2b, bb));
    }
    atomicAdd(&g_S[(size_t)n * PD + pi], sa);
    atomicAdd(&g_S[(size_t)n * PD + pi + 1], sb);
}

// ---------------- kernel 5: final scalar ----------------
// cx_sp is exactly the identity in fp32 (off-diagonal exponents <= -225 underflow),
// so m[pt] = 0.5 * (1 + cx_feat[pt][pt]) and only the dot diagonal is needed.
__global__ void k_final(float* __restrict__ out) {
    __shared__ float sh[256];
    __shared__ float lossn[NS];
    int tid = threadIdx.x;
    for (int n = 0; n < NS; n++) {
        float s = 0.0f;
        for (int p = tid; p < PD; p += 256) {
            float mn = g_colmin[(size_t)n * PD + p];
            float c1 = 5.0f / (mn + EPSF);
            float dmax = 1.0f - 2.0f * mn;
            float dd = __half2float(g_dot[((size_t)n * PD + p) * PD + p]);
            float cxf = fexp(c1 * (dd - dmax)) / g_S[(size_t)n * PD + p];
            s += 0.5f + 0.5f * cxf;
        }
        sh[tid] = s; __syncthreads();
        for (int o = 128; o > 0; o >>= 1) { if (tid < o) sh[tid] += sh[tid + o]; __syncthreads(); }
        if (tid == 0) lossn[n] = -logf(sh[0] * (1.0f / (float)PD));
        __syncthreads();
    }
    if (tid == 0) {
        float acc = 0.0f;
        for (int n = 0; n < NS; n++) acc += lossn[n];
        out[0] = acc * (1.0f / (float)NS);
    }
}

// ---------------- launch ----------------
extern "C" void kernel_launch(void* const* d_in, const int* in_sizes, int n_in,
                              void* d_out, int out_size) {
    const float* I = (const float*)d_in[0];
    const float* T = (const float*)d_in[1];
    float* out = (float*)d_out;

    cudaFuncSetAttribute(k_gemm, cudaFuncAttributeMaxDynamicSharedMemorySize, GEMM_SMEM_BYTES);

    k_mean<<<CD, 256>>>(T);
    k_norm2<<<dim3(PD / NP, NS, 2), 256>>>(I, T);
    k_gemm<<<GRID_GEMM, 512, GEMM_SMEM_BYTES>>>();
    k_sumcols<<<dim3(PD / 512, PD / 64, NS), 256>>>();
    k_final<<<1, 256>>>(out);
}

// round 8
// speedup vs baseline: 1.1565x; 1.0264x over previous
#include <cuda_runtime.h>
#include <cuda_fp16.h>
#include <cuda_bf16.h>
#include <cstdint>

// ---------------- problem constants ----------------
#define NS 2
#define CD 256
#define PD 4096            // 64*64
#define EPSF 1e-5f
#define LOG2E 1.4426950408889634f

// ---------------- device scratch (no runtime allocs allowed) ----------------
static __device__ __half   g_dot[(size_t)NS * PD * PD];   // 64 MiB: dot[n][pt][pi]
static __device__ uint8_t  g_Tn[(size_t)NS * PD * CD];    // normalized T, fp8 e4m3 x16, [n][p][c]
static __device__ uint8_t  g_In[(size_t)NS * PD * CD];    // normalized I, fp8 e4m3 x16, [n][p][c]
static __device__ float g_meanT[CD];
static __device__ float g_colmin[NS * PD];   // min over pt of raw=(1-dot)/2 per (n,pi); >=0
static __device__ float g_S[NS * PD];        // sum_pt exp(c1*(dot-dmax)) per (n,pi)

// ---------------- asm helpers (baseline sm_80/sm_89 ISA only) ----------------
__device__ __forceinline__ uint32_t smem_to_u32(const void* p) {
    uint32_t a;
    asm("{ .reg .u64 t; cvta.to.shared.u64 t, %1; cvt.u32.u64 %0, t; }" : "=r"(a) : "l"(p));
    return a;
}
#define CP_ASYNC16(dst, src) \
    asm volatile("cp.async.cg.shared.global [%0], [%1], 16;" :: "r"(dst), "l"(src) : "memory")
#define CP_COMMIT() asm volatile("cp.async.commit_group;" ::: "memory")
#define CP_WAIT(N)  asm volatile("cp.async.wait_group %0;" :: "n"(N) : "memory")
#define NAMED_BAR64(id) asm volatile("bar.sync %0, 64;" :: "r"(id) : "memory")

#define LDSM_X4(R, addr) \
    asm volatile("ldmatrix.sync.aligned.m8n8.x4.shared.b16 {%0,%1,%2,%3}, [%4];" \
        : "=r"((R)[0]), "=r"((R)[1]), "=r"((R)[2]), "=r"((R)[3]) : "r"(addr))

// fp8 e4m3 MMA: m16n8k32, A row-major (K-major), B col-major (K-major), f32 accum
#define MMA_FP8(D, A, B0, B1) \
    asm volatile("mma.sync.aligned.m16n8k32.row.col.f32.e4m3.e4m3.f32 " \
        "{%0,%1,%2,%3}, {%4,%5,%6,%7}, {%8,%9}, {%0,%1,%2,%3};" \
        : "+f"((D)[0]), "+f"((D)[1]), "+f"((D)[2]), "+f"((D)[3]) \
        : "r"((A)[0]), "r"((A)[1]), "r"((A)[2]), "r"((A)[3]), "r"(B0), "r"(B1))

// pack two floats -> e4m3x2 (lo = first elem, hi = second elem)
__device__ __forceinline__ uint16_t pack_e4m3(float lo, float hi) {
    uint16_t r;
    asm("cvt.rn.satfinite.e4m3x2.f32 %0, %1, %2;" : "=h"(r) : "f"(hi), "f"(lo));
    return r;
}
__device__ __forceinline__ float ex2(float x) {
    float r;
    asm("ex2.approx.ftz.f32 %0, %1;" : "=f"(r) : "f"(x));
    return r;
}
__device__ __forceinline__ float fexp(float x) {
    return ex2(fmaxf(x, -120.0f) * LOG2E);
}

// ---------------- kernel 1: meanT per channel (+ fused accumulator init) ----------------
__global__ void k_mean(const float* __restrict__ T) {
    int c = blockIdx.x;       // 256
    int tid = threadIdx.x;    // 256
    if (tid < 32) {           // 256 blocks x 32 = 8192 = NS*PD
        int i = c * 32 + tid;
        g_colmin[i] = 3.402823466e38f;
        g_S[i] = 0.0f;
    }
    float s = 0.0f;
    #pragma unroll
    for (int n = 0; n < NS; n++) {
        const float4* b4 = (const float4*)(T + ((size_t)n * CD + c) * PD);
        #pragma unroll
        for (int i = tid; i < PD / 4; i += 256) {
            float4 v = b4[i];
            s += v.x + v.y + v.z + v.w;
        }
    }
    __shared__ float sh[256];
    sh[tid] = s; __syncthreads();
    for (int o = 128; o > 0; o >>= 1) { if (tid < o) sh[tid] += sh[tid + o]; __syncthreads(); }
    if (tid == 0) g_meanT[c] = sh[0] * (1.0f / (float)(NS * PD));
}

// ---------------- kernel 2: center + normalize(+x16) + transpose -> fp8 ----------------
#define NP 32
#define BPITCH 260   // floats per p-row (256 + 4 pad)
__global__ void __launch_bounds__(256) k_norm2(const float* __restrict__ I,
                                               const float* __restrict__ T) {
    const float* X = blockIdx.z ? I : T;
    uint8_t* out = blockIdx.z ? g_In : g_Tn;
    int n = blockIdx.y;
    int p0 = blockIdx.x * NP;
    int tid = threadIdx.x;
    __shared__ float buf[NP][BPITCH];   // [p][c]
    __shared__ float nrm[8][NP];

    const float* base = X + (size_t)n * CD * PD + p0;
    #pragma unroll
    for (int it = 0; it < 8; it++) {
        int idx = it * 256 + tid;       // 2048 = 256 c * 8 float4
        int c = idx >> 3, j = idx & 7;
        float4 v = *(const float4*)(base + (size_t)c * PD + j * 4);
        float mc = g_meanT[c];
        buf[j * 4 + 0][c] = v.x - mc;
        buf[j * 4 + 1][c] = v.y - mc;
        buf[j * 4 + 2][c] = v.z - mc;
        buf[j * 4 + 3][c] = v.w - mc;
    }
    __syncthreads();
    {
        int p = tid >> 3, k = tid & 7;  // 32 p x 8 chunks
        float s = 0.0f;
        #pragma unroll
        for (int m = 0; m < 32; m++) { float v = buf[p][k * 32 + m]; s += v * v; }
        nrm[k][p] = s;
    }
    __syncthreads();
    if (tid < NP) {
        float t = 0.0f;
        #pragma unroll
        for (int k = 0; k < 8; k++) t += nrm[k][tid];
        nrm[0][tid] = rsqrtf(t) * 16.0f;   // x16 scale: e4m3 values ~O(1)
    }
    __syncthreads();
    uint8_t* ob = out + ((size_t)n * PD + p0) * CD;
    #pragma unroll
    for (int it = 0; it < 4; it++) {
        int idx = it * 256 + tid;       // 1024 = 32 p * 32 8-byte groups
        int p = idx >> 5, q = idx & 31;
        float sc = nrm[0][p];
        float4 v0 = *(float4*)&buf[p][q * 8];
        float4 v1 = *(float4*)&buf[p][q * 8 + 4];
        uint16_t h0 = pack_e4m3(v0.x * sc, v0.y * sc);
        uint16_t h1 = pack_e4m3(v0.z * sc, v0.w * sc);
        uint16_t h2 = pack_e4m3(v1.x * sc, v1.y * sc);
        uint16_t h3 = pack_e4m3(v1.z * sc, v1.w * sc);
        uint2 u;
        u.x = (uint32_t)h0 | ((uint32_t)h1 << 16);
        u.y = (uint32_t)h2 | ((uint32_t)h3 << 16);
        *(uint2*)(ob + (size_t)p * CD + q * 8) = u;
    }
}

// ---------------- kernel 3: persistent fp8 MMA GEMM, 128x128 tiles, 2 CTAs/SM ----------------
#define BM 128
#define BN 128
#define PITCH 144                 // 128 fp8 bytes + 16B pad
#define ASZ (BM * PITCH)          // 18432
#define BSZ (BN * PITCH)          // 18432
#define STG (ASZ + BSZ)           // 36864
#define EPI_OFF (2 * STG)         // 73728
#define EPITCH 272                // epilogue fp16 row pitch (128*2 + 16)
#define GEMM_SMEM_BYTES (EPI_OFF + BM * EPITCH)   // 73728 + 34816 = 108544
#define GRID_GEMM 296             // 2 CTAs per SM
#define NTILES (NS * (PD / BM) * (PD / BN))       // 2048

__device__ __forceinline__ void gemm_load_stage(
    uint32_t sb, int stage, int kc, int tid,
    const uint8_t* Asrc, const uint8_t* Bsrc) {
    uint32_t base = sb + stage * STG;
    #pragma unroll
    for (int i = 0; i < 4; i++) {               // A: 128 rows x 8 chunks = 1024
        int id = tid + i * 256;
        int row = id >> 3, g = id & 7;
        CP_ASYNC16(base + row * PITCH + g * 16, Asrc + (size_t)row * CD + kc * 128 + g * 16);
    }
    #pragma unroll
    for (int i = 0; i < 4; i++) {               // B: 128 rows x 8 chunks = 1024
        int id = tid + i * 256;
        int row = id >> 3, g = id & 7;
        CP_ASYNC16(base + ASZ + row * PITCH + g * 16, Bsrc + (size_t)row * CD + kc * 128 + g * 16);
    }
}

__device__ __forceinline__ void gemm_compute_chunk(uint32_t aB, uint32_t bB, float d[2][8][4]) {
    #pragma unroll
    for (int kk = 0; kk < 4; kk++) {   // 4 x k32 (32 bytes each)
        uint32_t a[2][4], b[4][4];
        LDSM_X4(a[0], aB + kk * 32);
        LDSM_X4(a[1], aB + 16 * PITCH + kk * 32);
        #pragma unroll
        for (int nb = 0; nb < 4; nb++)
            LDSM_X4(b[nb], bB + nb * 16 * PITCH + kk * 32);
        #pragma unroll
        for (int mi = 0; mi < 2; mi++)
            #pragma unroll
            for (int ni = 0; ni < 8; ni++) {
                uint32_t* bp = b[ni >> 1];
                MMA_FP8(d[mi][ni], a[mi], bp[(ni & 1) * 2], bp[(ni & 1) * 2 + 1]);
            }
    }
}

__device__ __forceinline__ void gemm_decode(int t, const uint8_t** A, const uint8_t** B,
                                            int* n2, int* pt0, int* pi0) {
    *n2 = t >> 10;                // 1024 tiles per sample
    int rem = t & 1023;
    *pt0 = (rem >> 5) * BM;       // 32 pt tiles
    *pi0 = (rem & 31) * BN;       // 32 pi tiles
    *A = g_Tn + ((size_t)(*n2) * PD + *pt0) * CD;
    *B = g_In + ((size_t)(*n2) * PD + *pi0) * CD;
}

__global__ void __launch_bounds__(256, 2) k_gemm() {
    extern __shared__ char smem[];
    uint32_t sb = smem_to_u32(smem);
    int tid = threadIdx.x, lane = tid & 31, wid = tid >> 5;

    int mw = wid & 3;               // m-group: 2 warps (wid&3 equal) own rows m0..m0+31
    int m0 = mw * 32;
    int n0 = (wid >> 2) * 64;       // 2 N-warps x 64 cols
    uint32_t aOff = (uint32_t)((m0 + (lane & 15)) * PITCH + (lane >> 4) * 16);
    uint32_t bOff = (uint32_t)(ASZ + (n0 + (lane & 7) + ((lane >> 4) * 8)) * PITCH
                               + ((lane >> 3) & 1) * 16);
    int gID = lane >> 2, tig = lane & 3;
    int gtid = (wid >> 2) * 32 + lane;   // 0..63 within m-group
    const float RS = 1.0f / 256.0f;      // undo the x16*x16 feature scaling

    int t = blockIdx.x;
    if (t >= NTILES) return;
    const uint8_t *Asrc, *Bsrc;
    int n2, pt0, pi0;
    gemm_decode(t, &Asrc, &Bsrc, &n2, &pt0, &pi0);

    gemm_load_stage(sb, 0, 0, tid, Asrc, Bsrc); CP_COMMIT();
    gemm_load_stage(sb, 1, 1, tid, Asrc, Bsrc); CP_COMMIT();

    while (true) {
        int tn = t + GRID_GEMM;
        bool more = (tn < NTILES);
        const uint8_t *An = nullptr, *Bn = nullptr;
        int nn2, npt0, npi0;
        if (more) gemm_decode(tn, &An, &Bn, &nn2, &npt0, &npi0);

        float d[2][8][4] = {};

        CP_WAIT(1); __syncthreads();
        gemm_compute_chunk(sb + aOff, sb + bOff, d);
        __syncthreads();
        if (more) { gemm_load_stage(sb, 0, 0, tid, An, Bn); CP_COMMIT(); }

        CP_WAIT(1); __syncthreads();
        gemm_compute_chunk(sb + STG + aOff, sb + STG + bOff, d);
        __syncthreads();
        if (more) { gemm_load_stage(sb, 1, 1, tid, An, Bn); CP_COMMIT(); }

        // ---- epilogue: per-m-group (named barriers, 64 thr), overlaps other groups + loads ----
        char* epi = smem + EPI_OFF;
        NAMED_BAR64(1 + mw);   // group's previous-tile epi reads complete before overwrite
        #pragma unroll
        for (int ni = 0; ni < 8; ni++) {
            float mx0 = -2.0f, mx1 = -2.0f;
            int col = n0 + ni * 8 + tig * 2;
            #pragma unroll
            for (int mi = 0; mi < 2; mi++) {
                float* dd = d[mi][ni];
                __half2 h01 = __floats2half2_rn(dd[0] * RS, dd[1] * RS);
                __half2 h23 = __floats2half2_rn(dd[2] * RS, dd[3] * RS);
                int row = m0 + mi * 16 + gID;
                *(__half2*)(epi + row * EPITCH + col * 2) = h01;
                *(__half2*)(epi + (row + 8) * EPITCH + col * 2) = h23;
                mx0 = fmaxf(mx0, fmaxf(__low2float(h01), __low2float(h23)));
                mx1 = fmaxf(mx1, fmaxf(__high2float(h01), __high2float(h23)));
            }
            #pragma unroll
            for (int o = 4; o < 32; o <<= 1) {
                mx0 = fmaxf(mx0, __shfl_xor_sync(0xffffffffu, mx0, o));
                mx1 = fmaxf(mx1, __shfl_xor_sync(0xffffffffu, mx1, o));
            }
            if (lane < 4) {
                int pi = pi0 + col;
                atomicMin((int*)&g_colmin[(size_t)n2 * PD + pi],
                          __float_as_int(0.5f - 0.5f * mx0));
                atomicMin((int*)&g_colmin[(size_t)n2 * PD + pi + 1],
                          __float_as_int(0.5f - 0.5f * mx1));
            }
        }
        NAMED_BAR64(1 + mw);   // group's epi rows fully written
        #pragma unroll
        for (int it = 0; it < 8; it++) {
            int idx = it * 64 + gtid;          // 512 = 32 rows x 16 uint4
            int r = m0 + (idx >> 4), q = idx & 15;
            uint4 v = *(uint4*)(epi + r * EPITCH + q * 16);
            *(uint4*)(g_dot + ((size_t)n2 * PD + pt0 + r) * PD + pi0 + q * 8) = v;
        }

        if (!more) break;
        t = tn; Asrc = An; Bsrc = Bn; n2 = nn2; pt0 = npt0; pi0 = npi0;
    }
}

// ---------------- kernel 4: column sums S[n][pi] = sum_pt exp(c1*(dot-dmax)) ----------------
// R4/R7-verified geometry: 1024 blocks, 64 rows/block, 2 cols/thread, unroll 16.
__global__ void __launch_bounds__(256) k_sumcols() {
    int n = (NS - 1) - (int)blockIdx.z;
    int pi = (blockIdx.x * 256 + threadIdx.x) * 2;
    int pt0 = PD - 64 - (int)blockIdx.y * 64;
    float2 mn2 = *(float2*)&g_colmin[(size_t)n * PD + pi];
    float c2a = (5.0f * LOG2E) / (mn2.x + EPSF), c2b = (5.0f * LOG2E) / (mn2.y + EPSF);
    float ba = -c2a * (1.0f - 2.0f * mn2.x);   // -c2*dmax
    float bb = -c2b * (1.0f - 2.0f * mn2.y);
    const __half2* col = (const __half2*)(g_dot + ((size_t)n * PD + pt0) * PD + pi);
    float sa = 0.0f, sb = 0.0f;
    #pragma unroll 16
    for (int r = 0; r < 64; r++) {
        float2 f = __half22float2(col[(size_t)r * (PD / 2)]);
        sa += ex2(fmaf(f.x, c2a, ba));
        sb += ex2(fmaf(f.y, c2b, bb));
    }
    atomicAdd(&g_S[(size_t)n * PD + pi], sa);
    atomicAdd(&g_S[(size_t)n * PD + pi + 1], sb);
}

// ---------------- kernel 5: final scalar ----------------
// cx_sp is exactly the identity in fp32 (off-diagonal exponents <= -225 underflow),
// so m[pt] = 0.5 * (1 + cx_feat[pt][pt]) and only the dot diagonal is needed.
__global__ void k_final(float* __restrict__ out) {
    __shared__ float sh[256];
    __shared__ float lossn[NS];
    int tid = threadIdx.x;
    for (int n = 0; n < NS; n++) {
        float s = 0.0f;
        for (int p = tid; p < PD; p += 256) {
            float mn = g_colmin[(size_t)n * PD + p];
            float c1 = 5.0f / (mn + EPSF);
            float dmax = 1.0f - 2.0f * mn;
            float dd = __half2float(g_dot[((size_t)n * PD + p) * PD + p]);
            float cxf = fexp(c1 * (dd - dmax)) / g_S[(size_t)n * PD + p];
            s += 0.5f + 0.5f * cxf;
        }
        sh[tid] = s; __syncthreads();
        for (int o = 128; o > 0; o >>= 1) { if (tid < o) sh[tid] += sh[tid + o]; __syncthreads(); }
        if (tid == 0) lossn[n] = -logf(sh[0] * (1.0f / (float)PD));
        __syncthreads();
    }
    if (tid == 0) {
        float acc = 0.0f;
        for (int n = 0; n < NS; n++) acc += lossn[n];
        out[0] = acc * (1.0f / (float)NS);
    }
}

// ---------------- launch ----------------
extern "C" void kernel_launch(void* const* d_in, const int* in_sizes, int n_in,
                              void* d_out, int out_size) {
    const float* I = (const float*)d_in[0];
    const float* T = (const float*)d_in[1];
    float* out = (float*)d_out;

    cudaFuncSetAttribute(k_gemm, cudaFuncAttributeMaxDynamicSharedMemorySize, GEMM_SMEM_BYTES);

    k_mean<<<CD, 256>>>(T);
    k_norm2<<<dim3(PD / NP, NS, 2), 256>>>(I, T);
    k_gemm<<<GRID_GEMM, 256, GEMM_SMEM_BYTES>>>();
    k_sumcols<<<dim3(PD / 512, PD / 64, NS), 256>>>();
    k_final<<<1, 256>>>(out);
}